// round 7
// baseline (speedup 1.0000x reference)
#include <cuda_runtime.h>
#include <cuda_bf16.h>
#include <cstdint>

// Problem constants: B=32, N=8192, C=512, K=128
#define PB   32
#define PN   8192
#define PC   512
#define PK   128
#define SEGS 32       // CTAs per batch
#define TPB  256      // threads per CTA = elements per CTA (SEGS*TPB = PN)

// Scratch (zero-init at module load; kernel restores zeros every launch).
__device__ int          g_stage[PB * PK];
__device__ unsigned int g_cnt[PB];
__device__ unsigned int g_done[PB];

__global__ void __launch_bounds__(TPB) fused_filter_kernel(
    const float* __restrict__ one_hot,
    const int*   __restrict__ id_ptr,
    float*       __restrict__ out)
{
    const int g   = blockIdx.x;          // 0 .. PB*SEGS-1
    const int b   = g >> 5;              // batch
    const int seg = g & (SEGS - 1);      // segment within batch
    const int t   = threadIdx.x;

    const int id = __ldg(id_ptr);
    const int n  = seg * TPB + t;        // position within batch
    const size_t idx = (size_t)b * PN + n;

    // ---- scattered gather of the id column (proven 74%-occ config) ----
    float v = __ldg(one_hot + idx * PC + id);

    // ---- block_id output (coalesced) ----
    out[idx] = v;

    // ---- stage hit positions, unordered; order restored by finisher ----
    if (v != 0.0f) {
        unsigned slot = atomicAdd(&g_cnt[b], 1u);
        if (slot < PK) g_stage[b * PK + slot] = n;
    }

    // ---- release this CTA's stage writes, then arrive on done-counter ----
    __threadfence();
    __syncthreads();

    __shared__ unsigned s_done;
    if (t == 0) s_done = atomicAdd(&g_done[b], 1u);
    __syncthreads();

    if (s_done != SEGS - 1) return;      // not the last CTA of this batch

    // ========== finisher CTA for batch b (never waits: all others done) ====
    __threadfence();                      // acquire side of the release chain

    __shared__ int s_vals[PK];
    if (t < PK)
        s_vals[t] = __ldcg((const int*)&g_stage[b * PK + t]);  // L2 read, bypass L1
    __syncthreads();

    if (t < PK) {
        const int myv = s_vals[t];
        int rank = 0;
#pragma unroll 16
        for (int j = 0; j < PK; j++)
            rank += (s_vals[j] < myv);
        out[(size_t)PB * PN + (size_t)b * PK + rank] = (float)myv;
    }

    // ---- reset scratch for the next graph replay ----
    if (t == 0) {
        g_cnt[b] = 0u;
        __threadfence();
        atomicExch(&g_done[b], 0u);
    }
}

extern "C" void kernel_launch(void* const* d_in, const int* in_sizes, int n_in,
                              void* d_out, int out_size)
{
    const float* one_hot = (const float*)d_in[0];
    const int*   id_ptr  = (const int*)d_in[1];
    float*       out     = (float*)d_out;

    (void)in_sizes; (void)n_in; (void)out_size;

    fused_filter_kernel<<<PB * SEGS, TPB>>>(one_hot, id_ptr, out);
}

// round 8
// speedup vs baseline: 1.8925x; 1.8925x over previous
#include <cuda_runtime.h>
#include <cuda_bf16.h>
#include <cstdint>

// Problem constants: B=32, N=8192, C=512, K=128
#define PB    32
#define PN    8192
#define PC    512
#define PK    128
#define SEGS  32        // CTAs per batch
#define TPB   256       // threads per CTA = elements per CTA (SEGS*TPB = PN)
#define WORDS 256       // bitmask words per batch (PN/32)

// Scratch (zero-init at module load; finisher restores zeros every launch).
__device__ unsigned int g_mask[PB * WORDS];
__device__ unsigned int g_done[PB];

__global__ void __launch_bounds__(TPB) fused_filter_kernel(
    const float* __restrict__ one_hot,
    const int*   __restrict__ id_ptr,
    float*       __restrict__ out)
{
    const int g    = blockIdx.x;         // 0 .. PB*SEGS-1
    const int b    = g >> 5;             // batch
    const int seg  = g & (SEGS - 1);     // segment within batch
    const int t    = threadIdx.x;
    const int lane = t & 31;
    const int wid  = t >> 5;             // 0..7

    const int id = __ldg(id_ptr);
    const int n  = seg * TPB + t;        // position within batch
    const size_t idx = (size_t)b * PN + n;

    // ---- scattered gather of the id column (R3's proven config) ----
    float v = __ldg(one_hot + idx * PC + id);

    // ---- block_id output (coalesced; never fenced) ----
    out[idx] = v;

    // ---- stage hit via bitmask atomic; consume return to guarantee the
    //      update is performed at L2 before this thread reaches the barrier.
    //      (old can never be all-ones — this thread's bit is clear in old —
    //      and even if it could, the guarded store is correctness-neutral.)
    if (v != 0.0f) {
        unsigned old = atomicOr(&g_mask[b * WORDS + (n >> 5)], 1u << (n & 31));
        if (old == 0xFFFFFFFFu) out[idx] = v;
    }

    __syncthreads();                      // all staging atomics complete (L2)

    __shared__ unsigned s_done;
    if (t == 0) s_done = atomicAdd(&g_done[b], 1u);
    __syncthreads();

    if (s_done != SEGS - 1) return;       // not the last CTA of this batch

    // ========== finisher CTA for batch b (wait-free: all others done) ======
    __threadfence();                      // acquire; single CTA, cheap

    // Each thread owns one 32-bit mask word = positions [t*32, t*32+32)
    unsigned w = __ldcg(&g_mask[b * WORDS + t]);
    int cnt = __popc(w);

    // Inclusive warp scan of per-word counts
    int inc = cnt;
#pragma unroll
    for (int d = 1; d < 32; d <<= 1) {
        int y = __shfl_up_sync(0xffffffffu, inc, d);
        if (lane >= d) inc += y;
    }

    __shared__ int s_wsum[8];
    if (lane == 31) s_wsum[wid] = inc;
    __syncthreads();

    if (wid == 0) {
        int wv = (lane < 8) ? s_wsum[lane] : 0;
        int winc = wv;
#pragma unroll
        for (int d = 1; d < 8; d <<= 1) {
            int y = __shfl_up_sync(0xffffffffu, winc, d);
            if (lane >= d) winc += y;
        }
        if (lane < 8) s_wsum[lane] = winc - wv;   // exclusive warp base
    }
    __syncthreads();

    int pos = s_wsum[wid] + (inc - cnt);          // exclusive thread base

    // Emit set-bit positions in ascending order (bitmask => sorted for free)
    float* oidx = out + (size_t)PB * PN + (size_t)b * PK;
    while (w) {
        int bit = __ffs(w) - 1;
        w &= w - 1;
        if (pos < PK) oidx[pos] = (float)(t * 32 + bit);
        pos++;
    }

    // ---- reset scratch for the next graph replay ----
    g_mask[b * WORDS + t] = 0u;
    if (t == 0) g_done[b] = 0u;
}

extern "C" void kernel_launch(void* const* d_in, const int* in_sizes, int n_in,
                              void* d_out, int out_size)
{
    const float* one_hot = (const float*)d_in[0];
    const int*   id_ptr  = (const int*)d_in[1];
    float*       out     = (float*)d_out;

    (void)in_sizes; (void)n_in; (void)out_size;

    fused_filter_kernel<<<PB * SEGS, TPB>>>(one_hot, id_ptr, out);
}